// round 8
// baseline (speedup 1.0000x reference)
#include <cuda_runtime.h>
#include <math.h>
#include <stdint.h>

static constexpr int kN  = 384;
static constexpr int kD  = 256;
static constexpr int kH  = 8;
static constexpr float kScale = 0.17677669529663687f;  // 1/sqrt(32)

typedef unsigned long long u64;

// ---------------- scratch (__device__ globals; no allocation) ----------------
__device__ __align__(16) float qx_g[kN * kD];
__device__ __align__(16) float kx_g[kN * kD];
__device__ __align__(16) float vx_g[kN * kD];
__device__ __align__(16) float cen_g[kN * kH];          // qx . bk_e
__device__ __align__(16) float cne_g[kN * kH];          // kx . bq_e
__device__ __align__(16) float u_g[kN * kH * kD];       // [i][h][d]
__device__ __align__(16) float w_g[kN * kH * kD];       // [n][h][d]
__device__ __align__(16) float PT_g[kN * kD * 9];       // [n][dp*18 + h*2 + par]
__device__ __align__(16) float g_part_g[3 * kN * kH * kD];
__device__ __align__(16) float sum_part_g[3 * kN * kH];

// ---------------- f32x2 packed helpers ---------------------------------------
__device__ __forceinline__ void fma2(u64& d, u64 a, u64 b)
{
    asm("fma.rn.f32x2 %0, %1, %2, %3;" : "=l"(d) : "l"(a), "l"(b), "l"(d));
}
__device__ __forceinline__ u64 pack2(float lo, float hi)
{
    u64 r; asm("mov.b64 %0, {%1, %2};" : "=l"(r) : "f"(lo), "f"(hi)); return r;
}
__device__ __forceinline__ float2 unpack2(u64 v)
{
    float2 f; asm("mov.b64 {%0, %1}, %2;" : "=f"(f.x), "=f"(f.y) : "l"(v)); return f;
}

__device__ __forceinline__ void cpa16(void* smem, const void* gmem)
{
    unsigned s = (unsigned)__cvta_generic_to_shared(smem);
    asm volatile("cp.async.ca.shared.global [%0], [%1], 16;\n" :: "r"(s), "l"(gmem));
}
#define CP_COMMIT() asm volatile("cp.async.commit_group;\n" ::: "memory")
#define CP_WAIT2()  asm volatile("cp.async.wait_group 2;\n" ::: "memory")

// ---------------- K1: qx/kx/vx projections + score constants ----------------
__global__ __launch_bounds__(256) void k1_proj(
    const float* __restrict__ x,
    const float* __restrict__ Wq, const float* __restrict__ bq,
    const float* __restrict__ Wk, const float* __restrict__ bk,
    const float* __restrict__ Wv, const float* __restrict__ bv,
    const float* __restrict__ bk_e, const float* __restrict__ bq_e)
{
    __shared__ float xs[kD];
    int i = blockIdx.x, c = threadIdx.x;
    xs[c] = x[i * kD + c];
    __syncthreads();
    int h = c >> 5, k = c & 31;
    const float* wq = Wq + h * 8192 + k;
    const float* wk = Wk + h * 8192 + k;
    const float* wv = Wv + h * 8192 + k;
    float q = 0.f, kk = 0.f, v = 0.f;
#pragma unroll 8
    for (int d = 0; d < kD; d++) {
        float xv = xs[d];
        q  = fmaf(xv, wq[d * 32], q);
        kk = fmaf(xv, wk[d * 32], kk);
        v  = fmaf(xv, wv[d * 32], v);
    }
    q += bq[c]; kk += bk[c]; v += bv[c];
    qx_g[i * kD + c] = q;
    kx_g[i * kD + c] = kk;
    vx_g[i * kD + c] = v;

    float ce = bk_e[c] * q;
    float cn = bq_e[c] * kk;
#pragma unroll
    for (int o = 16; o; o >>= 1) {
        ce += __shfl_xor_sync(0xffffffffu, ce, o);
        cn += __shfl_xor_sync(0xffffffffu, cn, o);
    }
    if (k == 0) { cen_g[i * kH + h] = ce; cne_g[i * kH + h] = cn; }
}

// ---------------- K1b: u / w / PT tables -------------------------------------
__global__ __launch_bounds__(256) void k1b_uwp(
    const float* __restrict__ Wk_e,
    const float* __restrict__ Wq_e,
    const float* __restrict__ WOe)
{
    __shared__ float qs[16 * 32], ks[16 * 32], vs[16 * 32];
    int ib = blockIdx.x, h = blockIdx.y;
    int d = threadIdx.x;
    for (int idx = threadIdx.x; idx < 512; idx += 256) {
        int ii = idx >> 5, k = idx & 31;
        int g = (ib * 16 + ii) * kD + h * 32 + k;
        qs[idx] = qx_g[g]; ks[idx] = kx_g[g]; vs[idx] = vx_g[g];
    }
    __syncthreads();

    float wr[32];
#pragma unroll
    for (int k = 0; k < 32; k++) wr[k] = Wk_e[h * 8192 + d * 32 + k];
    for (int ii = 0; ii < 16; ii++) {
        float a = 0.f;
#pragma unroll
        for (int k = 0; k < 32; k++) a = fmaf(wr[k], qs[ii * 32 + k], a);
        u_g[((ib * 16 + ii) * kH + h) * kD + d] = a;
    }
#pragma unroll
    for (int k = 0; k < 32; k++) wr[k] = Wq_e[h * 8192 + d * 32 + k];
    for (int ii = 0; ii < 16; ii++) {
        float a = 0.f;
#pragma unroll
        for (int k = 0; k < 32; k++) a = fmaf(wr[k], ks[ii * 32 + k], a);
        w_g[((ib * 16 + ii) * kH + h) * kD + d] = a;
    }
#pragma unroll
    for (int k = 0; k < 32; k++) wr[k] = WOe[(h * 32 + k) * kD + d];
    for (int ii = 0; ii < 16; ii++) {
        float a = 0.f;
#pragma unroll
        for (int k = 0; k < 32; k++) a = fmaf(wr[k], vs[ii * 32 + k], a);
        // pair-interleaved: [n][dp*18 + h*2 + (d&1)]
        PT_g[(size_t)(ib * 16 + ii) * 2304 + (d >> 1) * 18 + h * 2 + (d & 1)] = a;
    }
}

// ---------------- K_fused: pipelined scores/softmax/g/e_out ------------------
// 4 i-rows, 2 j per slot, 4-slot cp.async ring, 1 barrier/iter, 512 thr.
// Slot (float4): E 512 | W 1024 | PT 1152 | cne 4  = 2692 f4 = 43072 B.
static constexpr int STG_F4 = 2692;
static constexpr int FUSED_SMEM = 4 * STG_F4 * 16;   // 172288 B

__device__ __forceinline__ void kf_prefetch(float4* st, const float* e, int i0, int j0)
{
    int t = threadIdx.x;
#pragma unroll
    for (int k = 0; k < 6; k++) {
        int idx = t + k * 512;
        if (idx >= STG_F4) break;
        if (idx < 512) {
            int jq = idx >> 8, r = idx & 255;
            int ii = r >> 6, c = r & 63;
            cpa16(st + idx,
                  (const float4*)(e) + ((size_t)(i0 + ii) * kN + (j0 + jq)) * 64 + c);
        } else if (idx < 1536) {
            int r = idx - 512;
            int jq = r >> 9, q = r & 511;
            cpa16(st + idx, (const float4*)w_g + (size_t)(j0 + jq) * 512 + q);
        } else if (idx < 2688) {
            int r = idx - 1536;
            int jq = (r >= 576) ? 1 : 0;
            int q  = r - jq * 576;
            cpa16(st + idx, (const float4*)PT_g + (size_t)(j0 + jq) * 576 + q);
        } else {
            cpa16(st + idx, (const float4*)cne_g + (size_t)j0 * 2 + (idx - 2688));
        }
    }
}

__global__ __launch_bounds__(512, 1) void k_fused(
    const float* __restrict__ e, const float* __restrict__ bOe,
    float* __restrict__ e_out)
{
    extern __shared__ float4 smem4[];
    __shared__ u64   p2_s[2][2][32];     // (pe,pe) duplicated
    __shared__ u64   ai2_s[2][2][32];    // (ai,ai)
    __shared__ u64   aj2_s[2][2][32];    // (aj,aj)
    __shared__ float cen_s[32], cnei_s[32];

    int t = threadIdx.x;
    int i0 = blockIdx.x * 4;
    int ch = blockIdx.y;
    int jbase = ch * 128;

    int p = t >> 4, seg = t & 15;       // score: 32 (ii,h) pairs x 16 segs
    int ii_s = p >> 3, h_s = p & 7;
    int dp = t & 127, g = t >> 7;       // out: 128 d-pairs x 4 rows

    if (t < 32) { cen_s[t] = cen_g[i0 * 8 + t]; cnei_s[t] = cne_g[i0 * 8 + t]; }

    // loop-invariant registers (packed f32x2)
    ulonglong2 u2[4], wi2[4];
    {
        const ulonglong2* ub = (const ulonglong2*)u_g + ((size_t)(i0 + ii_s) * 8 + h_s) * 64;
        const ulonglong2* wb = (const ulonglong2*)w_g + ((size_t)(i0 + ii_s) * 8 + h_s) * 64;
#pragma unroll
        for (int k = 0; k < 4; k++) { u2[k] = ub[seg + 16 * k]; wi2[k] = wb[seg + 16 * k]; }
    }
    u64 Pi2[8];
#pragma unroll
    for (int h = 0; h < 8; h++)
        Pi2[h] = *(const u64*)&PT_g[(size_t)(i0 + g) * 2304 + dp * 18 + h * 2];
    u64 bo2 = *(const u64*)&bOe[2 * dp];
    u64 g2[8];
#pragma unroll
    for (int h = 0; h < 8; h++) g2[h] = 0ull;
    float run_sum = 0.f;

    kf_prefetch(smem4,          e, i0, jbase);     CP_COMMIT();
    kf_prefetch(smem4 + STG_F4, e, i0, jbase + 2); CP_COMMIT();

    for (int it = 0; it <= 64; it++) {
        __syncthreads();
        if (it + 2 < 64)
            kf_prefetch(smem4 + (size_t)((it + 2) & 3) * STG_F4, e, i0, jbase + (it + 2) * 2);
        CP_COMMIT();
        CP_WAIT2();

        if (it < 64) {
            // ---- score phase on slot it ----
            const float4* st4 = smem4 + (size_t)(it & 3) * STG_F4;
            int buf = it & 1;
            u64 acc2[6];
#pragma unroll
            for (int q = 0; q < 6; q++) acc2[q] = 0ull;
#pragma unroll
            for (int k = 0; k < 4; k++) {
                ulonglong2 uu = u2[k], wi = wi2[k];
#pragma unroll
                for (int jq = 0; jq < 2; jq++) {
                    ulonglong2 ev = *(const ulonglong2*)&st4[jq * 256 + ii_s * 64 + seg + 16 * k];
                    ulonglong2 wj = *(const ulonglong2*)&st4[512 + jq * 512 + h_s * 64 + seg + 16 * k];
                    u64* a = acc2 + jq * 3;
                    fma2(a[0], ev.x, uu.x); fma2(a[0], ev.y, uu.y);
                    fma2(a[1], ev.x, wi.x); fma2(a[1], ev.y, wi.y);
                    fma2(a[2], ev.x, wj.x); fma2(a[2], ev.y, wj.y);
                }
            }
            float acc[6];
#pragma unroll
            for (int q = 0; q < 6; q++) { float2 v = unpack2(acc2[q]); acc[q] = v.x + v.y; }
#pragma unroll
            for (int o = 1; o < 16; o <<= 1)
#pragma unroll
                for (int q = 0; q < 6; q++)
                    acc[q] += __shfl_xor_sync(0xffffffffu, acc[q], o);

            if ((seg & 7) == 0) {          // seg 0 -> jq 0, seg 8 -> jq 1
                int jq = seg >> 3;
                float pe = __expf((acc[jq * 3] + cen_s[p]) * kScale);
                run_sum += pe;
                p2_s[buf][jq][p] = pack2(pe, pe);
                float si = (acc[jq * 3 + 1] + cnei_s[p]) * kScale;
                float sj = (acc[jq * 3 + 2] + ((const float*)st4)[10752 + jq * 8 + h_s]) * kScale;
                float ei = __expf(si), ej = __expf(sj);
                float inv = 1.f / (ei + ej);
                ai2_s[buf][jq][p] = pack2(ei * inv, ei * inv);
                aj2_s[buf][jq][p] = pack2(ej * inv, ej * inv);
            }
        }

        if (it > 0) {
            // ---- g + out phase on slot it-1 (thread: d-pair dp, row g) ----
            const float* stf = (const float*)(smem4 + (size_t)((it - 1) & 3) * STG_F4);
            const float* ptf = stf + 6144;
            int bprev = (it - 1) & 1;
            int j0 = jbase + (it - 1) * 2;
#pragma unroll
            for (int jq = 0; jq < 2; jq++) {
                u64 ed2 = *(const u64*)&stf[jq * 1024 + g * 256 + 2 * dp];
#pragma unroll
                for (int h = 0; h < 8; h++)
                    fma2(g2[h], p2_s[bprev][jq][g * 8 + h], ed2);

                u64 o2 = bo2;
#pragma unroll
                for (int h = 0; h < 8; h++) {
                    u64 pj2 = *(const u64*)&ptf[jq * 2304 + dp * 18 + h * 2];
                    fma2(o2, ai2_s[bprev][jq][g * 8 + h], Pi2[h]);
                    fma2(o2, aj2_s[bprev][jq][g * 8 + h], pj2);
                }
                int j = j0 + jq;
                *(u64*)&e_out[((size_t)(i0 + g) * kN + j) * kD + 2 * dp] = o2;
            }
        }
    }

    // combine jq0/jq1 run_sum partials (seg0 holds jq0, seg8 holds jq1)
    run_sum += __shfl_xor_sync(0xffffffffu, run_sum, 8);

#pragma unroll
    for (int h = 0; h < 8; h++)
        *(u64*)&g_part_g[(((size_t)ch * kN + i0 + g) * 8 + h) * 256 + 2 * dp] = g2[h];
    if (seg == 0)
        sum_part_g[((size_t)ch * kN + i0 + ii_s) * 8 + h_s] = run_sum;
}

// ---------------- K3: reduce + x_out, 2 nodes/block --------------------------
__global__ __launch_bounds__(512) void k3_xout(
    const float* __restrict__ Wv_e, const float* __restrict__ bv_e,
    const float* __restrict__ WOx,  const float* __restrict__ bOx,
    float* __restrict__ x_out)
{
    __shared__ float gs[2048];
    __shared__ float xc[256];
    __shared__ float part[512];
    __shared__ float inv_s[8];
    int t = threadIdx.x;
    int c = t & 255, pr = t >> 8;

    for (int sub = 0; sub < 2; sub++) {
        int i = blockIdx.x * 2 + sub;

        if (t < 8) {
            float s = sum_part_g[(size_t)i * 8 + t]
                    + sum_part_g[((size_t)kN + i) * 8 + t]
                    + sum_part_g[((size_t)2 * kN + i) * 8 + t];
            inv_s[t] = 1.f / s;
        }
        __syncthreads();
#pragma unroll
        for (int r = 0; r < 4; r++) {
            int idx = t + r * 512;
            int h = idx >> 8;
            float a = g_part_g[((size_t)i * 8 + h) * 256 + (idx & 255)]
                    + g_part_g[(((size_t)kN + i) * 8 + h) * 256 + (idx & 255)]
                    + g_part_g[(((size_t)2 * kN + i) * 8 + h) * 256 + (idx & 255)];
            gs[idx] = a * inv_s[h];
        }
        __syncthreads();

        {
            int h = c >> 5, k = c & 31;
            const float* wv = Wv_e + h * 8192 + k;
            const float* gh = gs + h * 256;
            float a0 = 0.f, a1 = 0.f;
            int dbeg = pr * 128;
#pragma unroll 4
            for (int dd = dbeg; dd < dbeg + 128; dd += 2) {
                a0 = fmaf(gh[dd],     wv[dd * 32],       a0);
                a1 = fmaf(gh[dd + 1], wv[(dd + 1) * 32], a1);
            }
            part[t] = a0 + a1;
        }
        __syncthreads();
        if (t < 256) xc[t] = part[t] + part[t + 256] + bv_e[t];
        __syncthreads();

        {
            float o0 = 0.f, o1 = 0.f;
            int cbeg = pr * 128;
#pragma unroll 4
            for (int cc = cbeg; cc < cbeg + 128; cc += 2) {
                o0 = fmaf(xc[cc],     WOx[cc * kD + c],       o0);
                o1 = fmaf(xc[cc + 1], WOx[(cc + 1) * kD + c], o1);
            }
            part[t] = o0 + o1;
        }
        __syncthreads();
        if (t < 256) x_out[(size_t)i * kD + t] = part[t] + part[t + 256] + bOx[t];
        __syncthreads();
    }
}

// ---------------- launch -----------------------------------------------------
extern "C" void kernel_launch(void* const* d_in, const int* in_sizes, int n_in,
                              void* d_out, int out_size)
{
    (void)in_sizes; (void)n_in; (void)out_size;
    const float* x    = (const float*)d_in[0];
    const float* e    = (const float*)d_in[1];
    const float* Wq_x = (const float*)d_in[2];
    const float* bq_x = (const float*)d_in[3];
    const float* Wk_e = (const float*)d_in[4];
    const float* bk_e = (const float*)d_in[5];
    const float* Wv_e = (const float*)d_in[6];
    const float* bv_e = (const float*)d_in[7];
    const float* Wq_e = (const float*)d_in[8];
    const float* bq_e = (const float*)d_in[9];
    const float* Wk_x = (const float*)d_in[10];
    const float* bk_x = (const float*)d_in[11];
    const float* Wv_x = (const float*)d_in[12];
    const float* bv_x = (const float*)d_in[13];
    const float* WOx  = (const float*)d_in[14];
    const float* bOx  = (const float*)d_in[15];
    const float* WOe  = (const float*)d_in[16];
    const float* bOe  = (const float*)d_in[17];

    float* out   = (float*)d_out;
    float* x_out = out;                 // [384,256]
    float* e_out = out + kN * kD;       // [384,384,256]

    cudaFuncSetAttribute(k_fused, cudaFuncAttributeMaxDynamicSharedMemorySize, FUSED_SMEM);

    k1_proj<<<kN, 256>>>(x, Wq_x, bq_x, Wk_x, bk_x, Wv_x, bv_x, bk_e, bq_e);
    k1b_uwp<<<dim3(24, 8), 256>>>(Wk_e, Wq_e, WOe);
    k_fused<<<dim3(96, 3), 512, FUSED_SMEM>>>(e, bOe, e_out);
    k3_xout<<<kN / 2, 512>>>(Wv_e, bv_e, WOx, bOx, x_out);
}